// round 12
// baseline (speedup 1.0000x reference)
#include <cuda_runtime.h>
#include <cstdint>

// LinearTPReadOut: out[n] = w_tp/sqrt(3) * (1/128) * sum_i A_i(n)*B_i(n)
//   A_i(n) = sum_u x[n, 128+3u+i] * w_lin[u,0],  B_i with w_lin[u,1]
// x: (N,1152) f32, w_lin: (128,2) f32, w_tp: (1,) f32, out: (N,) f32
//
// Final-form variant: warp-local depth-3 prefetch, zero block barriers,
// zero slot reuse (no smem hazards). Warp w owns 3 consecutive rows and a
// private 3-slot buffer (1536B each). All 3 rows' cp.async.cg groups issue
// up front; compute row r after wait_group (2-r). Warps progress fully
// independently (decorrelated DRAM demand); 36KB smem -> ~6 blocks/SM
// (~75% occ) with 4.6KB in flight per warp.
// Loads: lane's 3 cp.async at dst lane*16, +512, +1024 -> 3x 512B-dense
// warp transactions, L1 bypassed, perfect sectors.
// Compute: lane l owns u=4l..4l+3 (12 floats at 48B stride from smem;
// conflict-free: 8-lane LDS.128 phase covers all 32 word banks).
// Weights: 8 regs/lane (2x LDG.128, L1-hit). Reduction: butterfly
// all-reduce B (15 shfl) + per-lane dot + reduce p (5 shfl).
//
// Context: four prior designs (R8/R9/R10/R11) all saturate ~6.3TB/s on this
// 1536B-read/3072B-skip pattern -- the chip's path-independent full-chip
// memory cap. This kernel sits within ~2% of the 307MB/6.33TB/s floor.

#define ROW_STRIDE_F 1152
#define COL_OFF      128
#define RPW          3                 // rows per warp

__global__ __launch_bounds__(256)
void lintp_kernel(const float* __restrict__ x,
                  const float* __restrict__ w_lin,
                  const float* __restrict__ w_tp,
                  float* __restrict__ out, int n)
{
    __shared__ float4 buf[8][RPW][96];   // per-warp slots, 36KB

    const int tid  = threadIdx.x;
    const int lane = tid & 31;
    const int warp = tid >> 5;

    // per-lane weights (u = 4l..4l+3): 8 registers
    const float4* wp = reinterpret_cast<const float4*>(w_lin) + 2 * lane;
    const float4 wA = __ldg(wp);      // w0[4l], w1[4l], w0[4l+1], w1[4l+1]
    const float4 wB = __ldg(wp + 1);  // w0[4l+2], w1[4l+2], w0[4l+3], w1[4l+3]
    const float scale = __ldg(w_tp) * 0.57735026918962576451f * (1.0f / 128.0f);

    const int row0 = blockIdx.x * (8 * RPW) + warp * RPW;  // 3 consecutive rows
    const uint32_t sbase =
        (uint32_t)__cvta_generic_to_shared(&buf[warp][0][0]) +
        (uint32_t)lane * 16u;

    // ---- issue all rows' loads (3 dense 512B cp.async.cg each) ----
    #pragma unroll
    for (int r = 0; r < RPW; r++) {
        int row = row0 + r;
        row = row < n ? row : n - 1;
        const float4* gp = reinterpret_cast<const float4*>(
            x + (size_t)row * ROW_STRIDE_F + COL_OFF) + lane;
        const uint32_t dst = sbase + (uint32_t)r * 1536u;
        asm volatile("cp.async.cg.shared.global [%0], [%1], 16;"
                     :: "r"(dst),         "l"(gp));
        asm volatile("cp.async.cg.shared.global [%0], [%1], 16;"
                     :: "r"(dst + 512u),  "l"(gp + 32));
        asm volatile("cp.async.cg.shared.global [%0], [%1], 16;"
                     :: "r"(dst + 1024u), "l"(gp + 64));
        asm volatile("cp.async.commit_group;");
    }

    #pragma unroll
    for (int r = 0; r < RPW; r++) {
        if (r == 0)      asm volatile("cp.async.wait_group 2;");
        else if (r == 1) asm volatile("cp.async.wait_group 1;");
        else             asm volatile("cp.async.wait_group 0;");
        __syncwarp();

        const float4* tp = &buf[warp][r][3 * lane];
        const float4 v0 = tp[0];
        const float4 v1 = tp[1];
        const float4 v2 = tp[2];

        //  v0 = {u0i0, u0i1, u0i2, u1i0}
        //  v1 = {u1i1, u1i2, u2i0, u2i1}
        //  v2 = {u2i2, u3i0, u3i1, u3i2}
        const float A0 = v0.x*wA.x + v0.w*wA.z + v1.z*wB.x + v2.y*wB.z;
        const float A1 = v0.y*wA.x + v1.x*wA.z + v1.w*wB.x + v2.z*wB.z;
        const float A2 = v0.z*wA.x + v1.y*wA.z + v2.x*wB.x + v2.w*wB.z;
        float B0 = v0.x*wA.y + v0.w*wA.w + v1.z*wB.y + v2.y*wB.w;
        float B1 = v0.y*wA.y + v1.x*wA.w + v1.w*wB.y + v2.z*wB.w;
        float B2 = v0.z*wA.y + v1.y*wA.w + v2.x*wB.y + v2.w*wB.w;

        #pragma unroll
        for (int m = 16; m > 0; m >>= 1) {
            B0 += __shfl_xor_sync(0xffffffffu, B0, m);
            B1 += __shfl_xor_sync(0xffffffffu, B1, m);
            B2 += __shfl_xor_sync(0xffffffffu, B2, m);
        }

        float p = A0 * B0;
        p = fmaf(A1, B1, p);
        p = fmaf(A2, B2, p);

        #pragma unroll
        for (int m = 16; m > 0; m >>= 1)
            p += __shfl_down_sync(0xffffffffu, p, m);

        const int row = row0 + r;
        if (lane == 0 && row < n)
            out[row] = scale * p;
    }
}

extern "C" void kernel_launch(void* const* d_in, const int* in_sizes, int n_in,
                              void* d_out, int out_size)
{
    const float* x     = (const float*)d_in[0];
    const float* w_lin = (const float*)d_in[1];
    const float* w_tp  = (const float*)d_in[2];
    float* out = (float*)d_out;

    const int n = in_sizes[0] / ROW_STRIDE_F;        // 200000
    const int rowsPerBlock = 8 * RPW;                // 24
    const int blocks = (n + rowsPerBlock - 1) / rowsPerBlock;   // 8334
    lintp_kernel<<<blocks, 256>>>(x, w_lin, w_tp, out, n);
}

// round 14
// speedup vs baseline: 1.0109x; 1.0109x over previous
#include <cuda_runtime.h>
#include <cstdint>

// LinearTPReadOut: out[n] = w_tp/sqrt(3) * (1/128) * sum_i A_i(n)*B_i(n)
//   A_i(n) = sum_u x[n, 128+3u+i] * w_lin[u,0],  B_i with w_lin[u,1]
// x: (N,1152) f32, w_lin: (128,2) f32, w_tp: (1,) f32, out: (N,) f32
//
// Best-known design (R11) at 128-thread CTAs: warp-local depth-2 prefetch,
// zero block barriers. Warp w owns rows {row0+2w, row0+2w+1} and a private
// 2-slot smem buffer (1536B each). Both rows' cp.async.cg groups issue up
// front; wait_group 1 -> compute row 0 (row 1 in flight); wait_group 0 ->
// compute row 1. Only __syncwarp (~23cyc) -- warps fully decorrelated.
// 4 warps/CTA, 12KB smem -> 16 CTAs/SM = full 64-warp occupancy with fine
// allocation granularity.
// Loads: lane's 3 cp.async at dst lane*16, +512, +1024 -> 3x 512B-dense
// warp transactions, L1 bypassed, perfect sectors.
// Compute: lane l owns u=4l..4l+3 (12 floats at 48B stride from smem;
// conflict-free: 8-lane LDS.128 phase covers all 32 word banks).
// Weights: 8 regs/lane (2x LDG.128, L1-hit). Reduction: butterfly
// all-reduce B (15 shfl) + per-lane dot + reduce p (5 shfl).
//
// Context: R8-R12 (burst/94%occ, warp-ring/61%, persistent-DB/63%,
// depth-2/82%, depth-3/62%) all saturate 6.1-6.33 TB/s on this
// 1536B-read/3072B-skip pattern -- the chip's effective ceiling here.
// 49.6us sits ~2% above the 307MB/6.33TB/s floor.

#define ROW_STRIDE_F 1152
#define COL_OFF      128
#define WARPS        4

__global__ __launch_bounds__(32 * WARPS)
void lintp_kernel(const float* __restrict__ x,
                  const float* __restrict__ w_lin,
                  const float* __restrict__ w_tp,
                  float* __restrict__ out, int n)
{
    __shared__ float4 buf[WARPS][2][96];   // per-warp 2-slot buffer, 12KB

    const int tid  = threadIdx.x;
    const int lane = tid & 31;
    const int warp = tid >> 5;

    // per-lane weights (u = 4l..4l+3): 8 registers
    const float4* wp = reinterpret_cast<const float4*>(w_lin) + 2 * lane;
    const float4 wA = __ldg(wp);      // w0[4l], w1[4l], w0[4l+1], w1[4l+1]
    const float4 wB = __ldg(wp + 1);  // w0[4l+2], w1[4l+2], w0[4l+3], w1[4l+3]
    const float scale = __ldg(w_tp) * 0.57735026918962576451f * (1.0f / 128.0f);

    const int row0 = blockIdx.x * (2 * WARPS) + 2 * warp;  // warp's first row
    const uint32_t sbase =
        (uint32_t)__cvta_generic_to_shared(&buf[warp][0][0]) +
        (uint32_t)lane * 16u;

    // ---- issue both rows' loads (3 dense 512B cp.async.cg each) ----
    #pragma unroll
    for (int r = 0; r < 2; r++) {
        int row = row0 + r;
        row = row < n ? row : n - 1;
        const float4* gp = reinterpret_cast<const float4*>(
            x + (size_t)row * ROW_STRIDE_F + COL_OFF) + lane;
        const uint32_t dst = sbase + (uint32_t)r * 1536u;
        asm volatile("cp.async.cg.shared.global [%0], [%1], 16;"
                     :: "r"(dst),         "l"(gp));
        asm volatile("cp.async.cg.shared.global [%0], [%1], 16;"
                     :: "r"(dst + 512u),  "l"(gp + 32));
        asm volatile("cp.async.cg.shared.global [%0], [%1], 16;"
                     :: "r"(dst + 1024u), "l"(gp + 64));
        asm volatile("cp.async.commit_group;");
    }

    #pragma unroll
    for (int r = 0; r < 2; r++) {
        if (r == 0)
            asm volatile("cp.async.wait_group 1;");   // row 1 still in flight
        else
            asm volatile("cp.async.wait_group 0;");
        __syncwarp();

        const float4* tp = &buf[warp][r][3 * lane];
        const float4 v0 = tp[0];
        const float4 v1 = tp[1];
        const float4 v2 = tp[2];

        //  v0 = {u0i0, u0i1, u0i2, u1i0}
        //  v1 = {u1i1, u1i2, u2i0, u2i1}
        //  v2 = {u2i2, u3i0, u3i1, u3i2}
        const float A0 = v0.x*wA.x + v0.w*wA.z + v1.z*wB.x + v2.y*wB.z;
        const float A1 = v0.y*wA.x + v1.x*wA.z + v1.w*wB.x + v2.z*wB.z;
        const float A2 = v0.z*wA.x + v1.y*wA.z + v2.x*wB.x + v2.w*wB.z;
        float B0 = v0.x*wA.y + v0.w*wA.w + v1.z*wB.y + v2.y*wB.w;
        float B1 = v0.y*wA.y + v1.x*wA.w + v1.w*wB.y + v2.z*wB.w;
        float B2 = v0.z*wA.y + v1.y*wA.w + v2.x*wB.y + v2.w*wB.w;

        #pragma unroll
        for (int m = 16; m > 0; m >>= 1) {
            B0 += __shfl_xor_sync(0xffffffffu, B0, m);
            B1 += __shfl_xor_sync(0xffffffffu, B1, m);
            B2 += __shfl_xor_sync(0xffffffffu, B2, m);
        }

        float p = A0 * B0;
        p = fmaf(A1, B1, p);
        p = fmaf(A2, B2, p);

        #pragma unroll
        for (int m = 16; m > 0; m >>= 1)
            p += __shfl_down_sync(0xffffffffu, p, m);

        const int row = row0 + r;
        if (lane == 0 && row < n)
            out[row] = scale * p;
    }
}

extern "C" void kernel_launch(void* const* d_in, const int* in_sizes, int n_in,
                              void* d_out, int out_size)
{
    const float* x     = (const float*)d_in[0];
    const float* w_lin = (const float*)d_in[1];
    const float* w_tp  = (const float*)d_in[2];
    float* out = (float*)d_out;

    const int n = in_sizes[0] / ROW_STRIDE_F;        // 200000
    const int rowsPerBlock = 2 * WARPS;              // 8
    const int blocks = (n + rowsPerBlock - 1) / rowsPerBlock;   // 25000
    lintp_kernel<<<blocks, 32 * WARPS>>>(x, w_lin, w_tp, out, n);
}

// round 15
// speedup vs baseline: 1.0168x; 1.0058x over previous
#include <cuda_runtime.h>
#include <cstdint>

// LinearTPReadOut: out[n] = w_tp/sqrt(3) * (1/128) * sum_i A_i(n)*B_i(n)
//   A_i(n) = sum_u x[n, 128+3u+i] * w_lin[u,0],  B_i with w_lin[u,1]
// x: (N,1152) f32, w_lin: (128,2) f32, w_tp: (1,) f32, out: (N,) f32
//
// FINAL KERNEL (converged at memory floor). Warp-local depth-2 prefetch,
// zero block barriers. Warp w owns rows {row0+2w, row0+2w+1} and a private
// 2-slot smem buffer (1536B each). Both rows' cp.async.cg groups issue up
// front; wait_group 1 -> compute row 0 (row 1 in flight); wait_group 0 ->
// compute row 1. Only __syncwarp for cross-lane smem visibility -- warps
// progress independently (decorrelated DRAM demand) at ~82% occupancy
// (24KB smem, 32 regs).
// Loads: lane's 3 cp.async at dst lane*16, +512, +1024 -> 3x 512B-dense
// warp transactions, L1 bypassed, perfect 4-sector wavefronts.
// Compute: lane l owns u=4l..4l+3 (12 floats at 48B stride from smem;
// conflict-free: 8-lane LDS.128 phase covers all 32 word banks).
// Weights: 8 regs/lane (2x LDG.128, L1-hit). Reduction: butterfly
// all-reduce B (15 shfl) + per-lane dot + reduce p (5 shfl).
//
// Evidence of convergence: six structurally distinct designs (R8-R14:
// block-burst 94% occ, warp-ring 61%, persistent double-buffer 63%,
// warp-depth2 82%, warp-depth3 62%, 128t-CTA 83%) all saturate
// 6.1-6.33 TB/s on this 1536B-read/3072B-skip pattern -- the chip's
// path-independent memory ceiling. Mandatory traffic 307.2MB / 6.33TB/s
// = 48.5us floor; this kernel measures 49.25us (ncu), ~1.5% above it.

#define ROW_STRIDE_F 1152
#define COL_OFF      128

__global__ __launch_bounds__(256)
void lintp_kernel(const float* __restrict__ x,
                  const float* __restrict__ w_lin,
                  const float* __restrict__ w_tp,
                  float* __restrict__ out, int n)
{
    __shared__ float4 buf[8][2][96];     // per-warp 2-slot buffer, 24KB

    const int tid  = threadIdx.x;
    const int lane = tid & 31;
    const int warp = tid >> 5;

    // per-lane weights (u = 4l..4l+3): 8 registers
    const float4* wp = reinterpret_cast<const float4*>(w_lin) + 2 * lane;
    const float4 wA = __ldg(wp);      // w0[4l], w1[4l], w0[4l+1], w1[4l+1]
    const float4 wB = __ldg(wp + 1);  // w0[4l+2], w1[4l+2], w0[4l+3], w1[4l+3]
    const float scale = __ldg(w_tp) * 0.57735026918962576451f * (1.0f / 128.0f);

    const int row0 = blockIdx.x * 16 + 2 * warp;   // this warp's first row
    const uint32_t sbase =
        (uint32_t)__cvta_generic_to_shared(&buf[warp][0][0]) +
        (uint32_t)lane * 16u;

    // ---- issue both rows' loads (3 dense 512B cp.async.cg each) ----
    #pragma unroll
    for (int r = 0; r < 2; r++) {
        int row = row0 + r;
        row = row < n ? row : n - 1;
        const float4* gp = reinterpret_cast<const float4*>(
            x + (size_t)row * ROW_STRIDE_F + COL_OFF) + lane;
        const uint32_t dst = sbase + (uint32_t)r * 1536u;
        asm volatile("cp.async.cg.shared.global [%0], [%1], 16;"
                     :: "r"(dst),         "l"(gp));
        asm volatile("cp.async.cg.shared.global [%0], [%1], 16;"
                     :: "r"(dst + 512u),  "l"(gp + 32));
        asm volatile("cp.async.cg.shared.global [%0], [%1], 16;"
                     :: "r"(dst + 1024u), "l"(gp + 64));
        asm volatile("cp.async.commit_group;");
    }

    #pragma unroll
    for (int r = 0; r < 2; r++) {
        if (r == 0)
            asm volatile("cp.async.wait_group 1;");   // row 1 still in flight
        else
            asm volatile("cp.async.wait_group 0;");
        __syncwarp();

        const float4* tp = &buf[warp][r][3 * lane];
        const float4 v0 = tp[0];
        const float4 v1 = tp[1];
        const float4 v2 = tp[2];

        //  v0 = {u0i0, u0i1, u0i2, u1i0}
        //  v1 = {u1i1, u1i2, u2i0, u2i1}
        //  v2 = {u2i2, u3i0, u3i1, u3i2}
        const float A0 = v0.x*wA.x + v0.w*wA.z + v1.z*wB.x + v2.y*wB.z;
        const float A1 = v0.y*wA.x + v1.x*wA.z + v1.w*wB.x + v2.z*wB.z;
        const float A2 = v0.z*wA.x + v1.y*wA.z + v2.x*wB.x + v2.w*wB.z;
        float B0 = v0.x*wA.y + v0.w*wA.w + v1.z*wB.y + v2.y*wB.w;
        float B1 = v0.y*wA.y + v1.x*wA.w + v1.w*wB.y + v2.z*wB.w;
        float B2 = v0.z*wA.y + v1.y*wA.w + v2.x*wB.y + v2.w*wB.w;

        #pragma unroll
        for (int m = 16; m > 0; m >>= 1) {
            B0 += __shfl_xor_sync(0xffffffffu, B0, m);
            B1 += __shfl_xor_sync(0xffffffffu, B1, m);
            B2 += __shfl_xor_sync(0xffffffffu, B2, m);
        }

        float p = A0 * B0;
        p = fmaf(A1, B1, p);
        p = fmaf(A2, B2, p);

        #pragma unroll
        for (int m = 16; m > 0; m >>= 1)
            p += __shfl_down_sync(0xffffffffu, p, m);

        const int row = row0 + r;
        if (lane == 0 && row < n)
            out[row] = scale * p;
    }
}

extern "C" void kernel_launch(void* const* d_in, const int* in_sizes, int n_in,
                              void* d_out, int out_size)
{
    const float* x     = (const float*)d_in[0];
    const float* w_lin = (const float*)d_in[1];
    const float* w_tp  = (const float*)d_in[2];
    float* out = (float*)d_out;

    const int n = in_sizes[0] / ROW_STRIDE_F;     // 200000
    const int blocks = (n + 15) / 16;             // 16 rows per block
    lintp_kernel<<<blocks, 256>>>(x, w_lin, w_tp, out, n);
}